// round 11
// baseline (speedup 1.0000x reference)
#include <cuda_runtime.h>
#include <math.h>

#define NB 64
#define NS 512
#define ND 1024
#define NH 1024
#define NK 4
#define DTC 0.05f

#define NCTA 128      // persistent CTAs (1/SM, must all be co-resident)

typedef unsigned long long ull;

// ---------------- packed f32x2 helpers (FFMA2 — PTX only) -------------------
__device__ __forceinline__ ull fma2(ull a, ull b, ull c) {
    ull d;
    asm("fma.rn.f32x2 %0, %1, %2, %3;" : "=l"(d) : "l"(a), "l"(b), "l"(c));
    return d;
}
__device__ __forceinline__ ull pack2(float x, float y) {
    ull d;
    asm("mov.b64 %0, {%1, %2};" : "=l"(d) : "r"(__float_as_uint(x)), "r"(__float_as_uint(y)));
    return d;
}
__device__ __forceinline__ float2 unpack2(ull v) {
    unsigned int lo, hi;
    asm("mov.b64 {%0, %1}, %2;" : "=r"(lo), "=r"(hi) : "l"(v));
    return make_float2(__uint_as_float(lo), __uint_as_float(hi));
}

// -------- device scratch (static allocation only; no cudaMalloc allowed) ----
__device__ float g_U[(size_t)NB * NS * NH];     // input projection, 128 MB
__device__ float g_hT[2 * NH * NB];             // double-buffered transposed h
__device__ float g_alpha[NB];
__device__ unsigned int g_count = 0;
__device__ unsigned int g_gen = 0;

// ---------------------------------------------------------------------------
__global__ void alpha_kernel(const float* __restrict__ comp,
                             const float* __restrict__ mw,
                             const float* __restrict__ mb,
                             const float* __restrict__ tau) {
    int b = threadIdx.x;
    if (b >= NB) return;
    float c = comp[b];
    float lg[NK];
    float mx = -1e30f;
#pragma unroll
    for (int k = 0; k < NK; k++) { lg[k] = c * mw[k] + mb[k]; mx = fmaxf(mx, lg[k]); }
    float se = 0.f;
#pragma unroll
    for (int k = 0; k < NK; k++) { lg[k] = expf(lg[k] - mx); se += lg[k]; }
    float mt = 0.f;
#pragma unroll
    for (int k = 0; k < NK; k++) mt += tau[k] * lg[k];
    mt /= se;
    g_alpha[b] = expf(-DTC / mt);
}

__global__ void zero_hT() {
    int i = blockIdx.x * blockDim.x + threadIdx.x;
    if (i < 2 * NH * NB) g_hT[i] = 0.f;
}

// ---------------------------------------------------------------------------
// U[m][n] = sum_k x[m][k] * W_in[n][k] + bias[n]
// M = 32768, N = 1024, K = 1024. 128x128 tile, Kt=8, 8x8/thread via FFMA2
// (accumulators paired along n), register prefetch of next K-tile.
// ---------------------------------------------------------------------------
__global__ __launch_bounds__(256) void gemm_u(const float* __restrict__ A,
                                              const float* __restrict__ W,
                                              const float* __restrict__ bias) {
    __shared__ float As[8][128];
    __shared__ float Bs[8][128];
    int tid = threadIdx.x;
    int m0 = blockIdx.y * 128;
    int n0 = blockIdx.x * 128;

    int lr = tid >> 1;            // 0..127 (tile row)
    int lk = (tid & 1) * 4;       // 0 or 4
    const float* Ag = A + (size_t)(m0 + lr) * ND + lk;
    const float* Bg = W + (size_t)(n0 + lr) * ND + lk;

    int tx = tid & 15;            // n direction (8 cols each)
    int ty = tid >> 4;            // m direction (8 rows each)

    ull acc[8][4];
#pragma unroll
    for (int i = 0; i < 8; i++)
#pragma unroll
        for (int j = 0; j < 4; j++) acc[i][j] = 0ull;

    float4 av = *(const float4*)(Ag);
    float4 bv = *(const float4*)(Bg);

    for (int kt = 0; kt < ND; kt += 8) {
        __syncthreads();
        As[lk + 0][lr] = av.x; As[lk + 1][lr] = av.y;
        As[lk + 2][lr] = av.z; As[lk + 3][lr] = av.w;
        Bs[lk + 0][lr] = bv.x; Bs[lk + 1][lr] = bv.y;
        Bs[lk + 2][lr] = bv.z; Bs[lk + 3][lr] = bv.w;
        __syncthreads();
        if (kt + 8 < ND) {                       // prefetch next tile
            av = *(const float4*)(Ag + kt + 8);
            bv = *(const float4*)(Bg + kt + 8);
        }
#pragma unroll
        for (int k = 0; k < 8; k++) {
            float a[8];
            *(float4*)&a[0] = *(const float4*)&As[k][ty * 8];
            *(float4*)&a[4] = *(const float4*)&As[k][ty * 8 + 4];
            ulonglong2 b01 = *(const ulonglong2*)&Bs[k][tx * 8];
            ulonglong2 b23 = *(const ulonglong2*)&Bs[k][tx * 8 + 4];
            ull bb0 = b01.x, bb1 = b01.y, bb2 = b23.x, bb3 = b23.y;
#pragma unroll
            for (int i = 0; i < 8; i++) {
                ull ai = pack2(a[i], a[i]);
                acc[i][0] = fma2(ai, bb0, acc[i][0]);
                acc[i][1] = fma2(ai, bb1, acc[i][1]);
                acc[i][2] = fma2(ai, bb2, acc[i][2]);
                acc[i][3] = fma2(ai, bb3, acc[i][3]);
            }
        }
    }

    float bv0[8];
#pragma unroll
    for (int j = 0; j < 8; j++) bv0[j] = bias[n0 + tx * 8 + j];
#pragma unroll
    for (int i = 0; i < 8; i++) {
        float* Cp = g_U + (size_t)(m0 + ty * 8 + i) * NH + n0 + tx * 8;
        float2 c0 = unpack2(acc[i][0]);
        float2 c1 = unpack2(acc[i][1]);
        float2 c2 = unpack2(acc[i][2]);
        float2 c3 = unpack2(acc[i][3]);
        float4 v0 = make_float4(c0.x + bv0[0], c0.y + bv0[1], c1.x + bv0[2], c1.y + bv0[3]);
        float4 v1 = make_float4(c2.x + bv0[4], c2.y + bv0[5], c3.x + bv0[6], c3.y + bv0[7]);
        *(float4*)(Cp)     = v0;
        *(float4*)(Cp + 4) = v1;
    }
}

// ---------------------------------------------------------------------------
// Flat grid barrier (measured equal to hierarchical; keep the simpler one).
// ---------------------------------------------------------------------------
__device__ __forceinline__ void grid_barrier() {
    __syncthreads();
    if (threadIdx.x == 0) {
        volatile unsigned int* genp = &g_gen;
        unsigned int g = *genp;
        __threadfence();                       // release this CTA's writes
        unsigned int a = atomicAdd(&g_count, 1u);
        if (a == NCTA - 1) {
            *(volatile unsigned int*)&g_count = 0;
            __threadfence();
            atomicAdd(&g_gen, 1u);             // release all
        } else {
            while (*genp == g) __nanosleep(16);
            __threadfence();                   // acquire
        }
    }
    __syncthreads();
}

// ---------------------------------------------------------------------------
// Persistent recurrent kernel. 128 CTAs (32 j-groups x 4 batch-groups),
// 512 threads = 16 warps = 16 k-slices of 64 (R7 inner loop, doubled warps
// for latency hiding). Per thread: 4j x 4b FFMA2 register tile over its
// warp's k-slice, then smem reduction over the 16 slices. W_rec^T slice
// (128 KB) resident in smem; h double-buffered in L2 (transposed layout).
// ---------------------------------------------------------------------------
__global__ __launch_bounds__(512, 1) void liquid_kernel(const float* __restrict__ Wr,
                                                        float* __restrict__ out) {
    extern __shared__ float smem[];
    float* Wt  = smem;                   // [1024][32]  W_rec^T slice, 128 KB
    float* hs  = smem + 1024 * 32;       // [1024][16]  staged h^T slice, 64 KB
    float* red = smem + 1024 * 48;       // [16][512]   k-slice partials, 32 KB

    int cta = blockIdx.x;
    int jg = cta & 31;                   // 32 j-groups
    int bg = cta >> 5;                   // 4 batch-groups
    int j0 = jg * 32;
    int b0 = bg * 16;
    int tid  = threadIdx.x;
    int w    = tid >> 5;                 // warp = k-slice (0..15)
    int lane = tid & 31;
    int tj = lane >> 2;                  // 0..7  -> j = j0 + 4*tj
    int tb = lane & 3;                   // 0..3  -> b = b0 + 4*tb
    int ks = w * 64;                     // this warp's k-slice start

    // ---- one-time: W_rec rows j0..j0+31, transposed into SMEM [k][j] ----
    {
        int jl = tid >> 4;               // 0..31 (j within slice)
        int c  = tid & 15;               // 4-float k chunk selector
        const float* wg = Wr + (size_t)(j0 + jl) * NH + c * 4;
#pragma unroll 4
        for (int q = 0; q < 16; q++) {
            float4 v = *(const float4*)(wg + q * 64);
            int kb = c * 4 + q * 64;
            Wt[(kb + 0) * 32 + jl] = v.x;
            Wt[(kb + 1) * 32 + jl] = v.y;
            Wt[(kb + 2) * 32 + jl] = v.z;
            Wt[(kb + 3) * 32 + jl] = v.w;
        }
    }

    // ---- epilogue assignment: thread owns output (bo, jo); red idx = tid ----
    int bl = tid >> 5;                   // 0..15
    int jl2 = tid & 31;                  // 0..31
    int bo = b0 + bl;
    int jo = j0 + jl2;
    float aa = g_alpha[bo];
    float na = 1.f - aa;
    float h = 0.f;                       // persistent h state in register
    size_t orow = (size_t)bo * NS;       // out/U row base (in NH units)

    __syncthreads();

    int src_r = lane >> 2;               // staging row-within-8 (0..7)
    int src_c = lane & 3;                // staging float4 chunk

    for (int t = 0; t < NS; t++) {
        const float* rbuf = g_hT + (size_t)(t & 1) * NH * NB;
        float*       wbuf = g_hT + (size_t)((t + 1) & 1) * NH * NB;

        // ---- prefetch this step's U early (latency off critical path) ----
        size_t ro = (orow + t) * NH + jo;
        float u = g_U[ro];

        // ---- per-warp stage: own 64k x 16b h^T slice into SMEM (via L2) ----
        __syncwarp();
#pragma unroll
        for (int i = 0; i < 8; i++) {
            int row = ks + src_r + 8 * i;
            float4 v = __ldcg((const float4*)(rbuf + (size_t)row * NB + b0) + src_c);
            *((float4*)(hs + row * 16) + src_c) = v;
        }
        __syncwarp();

        // ---- 4j x 4b FFMA2 tile over this warp's 64-k slice ----
        ull c00 = 0, c01 = 0, c10 = 0, c11 = 0, c20 = 0, c21 = 0, c30 = 0, c31 = 0;
        const float* wp = Wt + ks * 32 + 4 * tj;
        const float* hp = hs + ks * 16 + 4 * tb;
#pragma unroll 8
        for (int k = 0; k < 64; k++) {
            ulonglong2 wv = *(const ulonglong2*)(wp + k * 32);   // 4 j values
            float4    hv  = *(const float4*)(hp + k * 16);       // 4 b values
            ull hb0 = pack2(hv.x, hv.x);
            ull hb1 = pack2(hv.y, hv.y);
            ull hb2 = pack2(hv.z, hv.z);
            ull hb3 = pack2(hv.w, hv.w);
            c00 = fma2(hb0, wv.x, c00); c01 = fma2(hb0, wv.y, c01);
            c10 = fma2(hb1, wv.x, c10); c11 = fma2(hb1, wv.y, c11);
            c20 = fma2(hb2, wv.x, c20); c21 = fma2(hb2, wv.y, c21);
            c30 = fma2(hb3, wv.x, c30); c31 = fma2(hb3, wv.y, c31);
        }

        // ---- store k-slice partials: red[w][ (4tb+bi)*32 + 4tj + 2jp ] ----
        {
            ull* rp = (ull*)(red + w * 512 + 4 * tb * 32 + 4 * tj);
            rp[0]  = c00; rp[1]  = c01;   // bi=0
            rp[16] = c10; rp[17] = c11;   // bi=1 (+32 floats)
            rp[32] = c20; rp[33] = c21;   // bi=2
            rp[48] = c30; rp[49] = c31;   // bi=3
        }
        __syncthreads();

        // ---- reduce 16 slices, add u_t, tanh, state update, stores ----
        float s = 0.f;
#pragma unroll
        for (int ww = 0; ww < 16; ww++) s += red[ww * 512 + tid];
        h = aa * h + na * tanhf(s + u);
        __stcg(wbuf + (size_t)jo * NB + bo, h);   // state first (others need it)
        out[ro] = h;

        grid_barrier();
    }

    // ---- h_final appended after output[B,S,H] ----
    out[(size_t)NB * NS * NH + (size_t)bo * NH + jo] = h;
}

// ---------------------------------------------------------------------------
extern "C" void kernel_launch(void* const* d_in, const int* in_sizes, int n_in,
                              void* d_out, int out_size) {
    const float* x    = (const float*)d_in[0];
    const float* comp = (const float*)d_in[1];
    const float* Wrec = (const float*)d_in[2];
    const float* Win  = (const float*)d_in[3];
    const float* bias = (const float*)d_in[4];
    const float* tau  = (const float*)d_in[5];
    const float* mw   = (const float*)d_in[6];
    const float* mb   = (const float*)d_in[7];
    float* out = (float*)d_out;

    const int smem_bytes = (1024 * 32 + 1024 * 16 + 16 * 512) * (int)sizeof(float); // 229376
    cudaFuncSetAttribute(liquid_kernel, cudaFuncAttributeMaxDynamicSharedMemorySize,
                         smem_bytes);

    alpha_kernel<<<1, 64>>>(comp, mw, mb, tau);
    zero_hT<<<(2 * NH * NB + 1023) / 1024, 1024>>>();
    dim3 gemm_grid(NH / 128, (NB * NS) / 128);   // (8, 256)
    gemm_u<<<gemm_grid, 256>>>(x, Win, bias);
    liquid_kernel<<<NCTA, 512, smem_bytes>>>(Wrec, out);
}

// round 12
// speedup vs baseline: 1.0158x; 1.0158x over previous
#include <cuda_runtime.h>
#include <math.h>

#define NB 64
#define NS 512
#define ND 1024
#define NH 1024
#define NK 4
#define DTC 0.05f

#define NCTA 128      // persistent CTAs (1/SM, must all be co-resident)

typedef unsigned long long ull;

// ---------------- packed f32x2 helpers (FFMA2 — PTX only) -------------------
__device__ __forceinline__ ull fma2(ull a, ull b, ull c) {
    ull d;
    asm("fma.rn.f32x2 %0, %1, %2, %3;" : "=l"(d) : "l"(a), "l"(b), "l"(c));
    return d;
}
__device__ __forceinline__ ull pack2(float x, float y) {
    ull d;
    asm("mov.b64 %0, {%1, %2};" : "=l"(d) : "r"(__float_as_uint(x)), "r"(__float_as_uint(y)));
    return d;
}
__device__ __forceinline__ float2 unpack2(ull v) {
    unsigned int lo, hi;
    asm("mov.b64 {%0, %1}, %2;" : "=r"(lo), "=r"(hi) : "l"(v));
    return make_float2(__uint_as_float(lo), __uint_as_float(hi));
}

// -------- device scratch (static allocation only; no cudaMalloc allowed) ----
__device__ float g_U[(size_t)NB * NS * NH];     // input projection, 128 MB
__device__ float g_hT[2 * NH * NB];             // double-buffered transposed h
__device__ float g_alpha[NB];
__device__ unsigned int g_count = 0;
__device__ unsigned int g_gen = 0;

// ---------------------------------------------------------------------------
__global__ void alpha_kernel(const float* __restrict__ comp,
                             const float* __restrict__ mw,
                             const float* __restrict__ mb,
                             const float* __restrict__ tau) {
    int b = threadIdx.x;
    if (b >= NB) return;
    float c = comp[b];
    float lg[NK];
    float mx = -1e30f;
#pragma unroll
    for (int k = 0; k < NK; k++) { lg[k] = c * mw[k] + mb[k]; mx = fmaxf(mx, lg[k]); }
    float se = 0.f;
#pragma unroll
    for (int k = 0; k < NK; k++) { lg[k] = expf(lg[k] - mx); se += lg[k]; }
    float mt = 0.f;
#pragma unroll
    for (int k = 0; k < NK; k++) mt += tau[k] * lg[k];
    mt /= se;
    g_alpha[b] = expf(-DTC / mt);
}

__global__ void zero_hT() {
    int i = blockIdx.x * blockDim.x + threadIdx.x;
    if (i < 2 * NH * NB) g_hT[i] = 0.f;
}

// ---------------------------------------------------------------------------
// U[m][n] = sum_k x[m][k] * W_in[n][k] + bias[n]
// M = 32768, N = 1024, K = 1024. 128x128 tile, Kt=8, 8x8/thread via FFMA2
// (accumulators paired along n), register prefetch of next K-tile.
// ---------------------------------------------------------------------------
__global__ __launch_bounds__(256) void gemm_u(const float* __restrict__ A,
                                              const float* __restrict__ W,
                                              const float* __restrict__ bias) {
    __shared__ float As[8][128];
    __shared__ float Bs[8][128];
    int tid = threadIdx.x;
    int m0 = blockIdx.y * 128;
    int n0 = blockIdx.x * 128;

    int lr = tid >> 1;            // 0..127 (tile row)
    int lk = (tid & 1) * 4;       // 0 or 4
    const float* Ag = A + (size_t)(m0 + lr) * ND + lk;
    const float* Bg = W + (size_t)(n0 + lr) * ND + lk;

    int tx = tid & 15;            // n direction (8 cols each)
    int ty = tid >> 4;            // m direction (8 rows each)

    ull acc[8][4];
#pragma unroll
    for (int i = 0; i < 8; i++)
#pragma unroll
        for (int j = 0; j < 4; j++) acc[i][j] = 0ull;

    float4 av = *(const float4*)(Ag);
    float4 bv = *(const float4*)(Bg);

    for (int kt = 0; kt < ND; kt += 8) {
        __syncthreads();
        As[lk + 0][lr] = av.x; As[lk + 1][lr] = av.y;
        As[lk + 2][lr] = av.z; As[lk + 3][lr] = av.w;
        Bs[lk + 0][lr] = bv.x; Bs[lk + 1][lr] = bv.y;
        Bs[lk + 2][lr] = bv.z; Bs[lk + 3][lr] = bv.w;
        __syncthreads();
        if (kt + 8 < ND) {                       // prefetch next tile
            av = *(const float4*)(Ag + kt + 8);
            bv = *(const float4*)(Bg + kt + 8);
        }
#pragma unroll
        for (int k = 0; k < 8; k++) {
            float a[8];
            *(float4*)&a[0] = *(const float4*)&As[k][ty * 8];
            *(float4*)&a[4] = *(const float4*)&As[k][ty * 8 + 4];
            ulonglong2 b01 = *(const ulonglong2*)&Bs[k][tx * 8];
            ulonglong2 b23 = *(const ulonglong2*)&Bs[k][tx * 8 + 4];
            ull bb0 = b01.x, bb1 = b01.y, bb2 = b23.x, bb3 = b23.y;
#pragma unroll
            for (int i = 0; i < 8; i++) {
                ull ai = pack2(a[i], a[i]);
                acc[i][0] = fma2(ai, bb0, acc[i][0]);
                acc[i][1] = fma2(ai, bb1, acc[i][1]);
                acc[i][2] = fma2(ai, bb2, acc[i][2]);
                acc[i][3] = fma2(ai, bb3, acc[i][3]);
            }
        }
    }

    float bv0[8];
#pragma unroll
    for (int j = 0; j < 8; j++) bv0[j] = bias[n0 + tx * 8 + j];
#pragma unroll
    for (int i = 0; i < 8; i++) {
        float* Cp = g_U + (size_t)(m0 + ty * 8 + i) * NH + n0 + tx * 8;
        float2 c0 = unpack2(acc[i][0]);
        float2 c1 = unpack2(acc[i][1]);
        float2 c2 = unpack2(acc[i][2]);
        float2 c3 = unpack2(acc[i][3]);
        float4 v0 = make_float4(c0.x + bv0[0], c0.y + bv0[1], c1.x + bv0[2], c1.y + bv0[3]);
        float4 v1 = make_float4(c2.x + bv0[4], c2.y + bv0[5], c3.x + bv0[6], c3.y + bv0[7]);
        *(float4*)(Cp)     = v0;
        *(float4*)(Cp + 4) = v1;
    }
}

// ---------------------------------------------------------------------------
// Flat grid barrier (measured equal to hierarchical; keep the simpler one).
// ---------------------------------------------------------------------------
__device__ __forceinline__ void grid_barrier() {
    __syncthreads();
    if (threadIdx.x == 0) {
        volatile unsigned int* genp = &g_gen;
        unsigned int g = *genp;
        __threadfence();                       // release this CTA's writes
        unsigned int a = atomicAdd(&g_count, 1u);
        if (a == NCTA - 1) {
            *(volatile unsigned int*)&g_count = 0;
            __threadfence();
            atomicAdd(&g_gen, 1u);             // release all
        } else {
            while (*genp == g) __nanosleep(16);
            __threadfence();                   // acquire
        }
    }
    __syncthreads();
}

// ---------------------------------------------------------------------------
// Persistent recurrent kernel. 128 CTAs (32 j-groups x 4 batch-groups),
// 512 threads = 16 warps = 16 k-slices of 64 (R7 inner loop, doubled warps
// for latency hiding). Per thread: 4j x 4b FFMA2 register tile over its
// warp's k-slice, then smem reduction over the 16 slices. W_rec^T slice
// (128 KB) resident in smem; h double-buffered in L2 (transposed layout).
// ---------------------------------------------------------------------------
__global__ __launch_bounds__(512, 1) void liquid_kernel(const float* __restrict__ Wr,
                                                        float* __restrict__ out) {
    extern __shared__ float smem[];
    float* Wt  = smem;                   // [1024][32]  W_rec^T slice, 128 KB
    float* hs  = smem + 1024 * 32;       // [1024][16]  staged h^T slice, 64 KB
    float* red = smem + 1024 * 48;       // [16][512]   k-slice partials, 32 KB

    int cta = blockIdx.x;
    int jg = cta & 31;                   // 32 j-groups
    int bg = cta >> 5;                   // 4 batch-groups
    int j0 = jg * 32;
    int b0 = bg * 16;
    int tid  = threadIdx.x;
    int w    = tid >> 5;                 // warp = k-slice (0..15)
    int lane = tid & 31;
    int tj = lane >> 2;                  // 0..7  -> j = j0 + 4*tj
    int tb = lane & 3;                   // 0..3  -> b = b0 + 4*tb
    int ks = w * 64;                     // this warp's k-slice start

    // ---- one-time: W_rec rows j0..j0+31, transposed into SMEM [k][j] ----
    {
        int jl = tid >> 4;               // 0..31 (j within slice)
        int c  = tid & 15;               // 4-float k chunk selector
        const float* wg = Wr + (size_t)(j0 + jl) * NH + c * 4;
#pragma unroll 4
        for (int q = 0; q < 16; q++) {
            float4 v = *(const float4*)(wg + q * 64);
            int kb = c * 4 + q * 64;
            Wt[(kb + 0) * 32 + jl] = v.x;
            Wt[(kb + 1) * 32 + jl] = v.y;
            Wt[(kb + 2) * 32 + jl] = v.z;
            Wt[(kb + 3) * 32 + jl] = v.w;
        }
    }

    // ---- epilogue assignment: thread owns output (bo, jo); red idx = tid ----
    int bl = tid >> 5;                   // 0..15
    int jl2 = tid & 31;                  // 0..31
    int bo = b0 + bl;
    int jo = j0 + jl2;
    float aa = g_alpha[bo];
    float na = 1.f - aa;
    float h = 0.f;                       // persistent h state in register
    size_t orow = (size_t)bo * NS;       // out/U row base (in NH units)

    __syncthreads();

    int src_r = lane >> 2;               // staging row-within-8 (0..7)
    int src_c = lane & 3;                // staging float4 chunk

    for (int t = 0; t < NS; t++) {
        const float* rbuf = g_hT + (size_t)(t & 1) * NH * NB;
        float*       wbuf = g_hT + (size_t)((t + 1) & 1) * NH * NB;

        // ---- prefetch this step's U early (latency off critical path) ----
        size_t ro = (orow + t) * NH + jo;
        float u = g_U[ro];

        // ---- per-warp stage: own 64k x 16b h^T slice into SMEM (via L2) ----
        __syncwarp();
#pragma unroll
        for (int i = 0; i < 8; i++) {
            int row = ks + src_r + 8 * i;
            float4 v = __ldcg((const float4*)(rbuf + (size_t)row * NB + b0) + src_c);
            *((float4*)(hs + row * 16) + src_c) = v;
        }
        __syncwarp();

        // ---- 4j x 4b FFMA2 tile over this warp's 64-k slice ----
        ull c00 = 0, c01 = 0, c10 = 0, c11 = 0, c20 = 0, c21 = 0, c30 = 0, c31 = 0;
        const float* wp = Wt + ks * 32 + 4 * tj;
        const float* hp = hs + ks * 16 + 4 * tb;
#pragma unroll 8
        for (int k = 0; k < 64; k++) {
            ulonglong2 wv = *(const ulonglong2*)(wp + k * 32);   // 4 j values
            float4    hv  = *(const float4*)(hp + k * 16);       // 4 b values
            ull hb0 = pack2(hv.x, hv.x);
            ull hb1 = pack2(hv.y, hv.y);
            ull hb2 = pack2(hv.z, hv.z);
            ull hb3 = pack2(hv.w, hv.w);
            c00 = fma2(hb0, wv.x, c00); c01 = fma2(hb0, wv.y, c01);
            c10 = fma2(hb1, wv.x, c10); c11 = fma2(hb1, wv.y, c11);
            c20 = fma2(hb2, wv.x, c20); c21 = fma2(hb2, wv.y, c21);
            c30 = fma2(hb3, wv.x, c30); c31 = fma2(hb3, wv.y, c31);
        }

        // ---- store k-slice partials: red[w][ (4tb+bi)*32 + 4tj + 2jp ] ----
        {
            ull* rp = (ull*)(red + w * 512 + 4 * tb * 32 + 4 * tj);
            rp[0]  = c00; rp[1]  = c01;   // bi=0
            rp[16] = c10; rp[17] = c11;   // bi=1 (+32 floats)
            rp[32] = c20; rp[33] = c21;   // bi=2
            rp[48] = c30; rp[49] = c31;   // bi=3
        }
        __syncthreads();

        // ---- reduce 16 slices, add u_t, tanh, state update, stores ----
        float s = 0.f;
#pragma unroll
        for (int ww = 0; ww < 16; ww++) s += red[ww * 512 + tid];
        h = aa * h + na * tanhf(s + u);
        __stcg(wbuf + (size_t)jo * NB + bo, h);   // state first (others need it)
        out[ro] = h;

        grid_barrier();
    }

    // ---- h_final appended after output[B,S,H] ----
    out[(size_t)NB * NS * NH + (size_t)bo * NH + jo] = h;
}

// ---------------------------------------------------------------------------
extern "C" void kernel_launch(void* const* d_in, const int* in_sizes, int n_in,
                              void* d_out, int out_size) {
    const float* x    = (const float*)d_in[0];
    const float* comp = (const float*)d_in[1];
    const float* Wrec = (const float*)d_in[2];
    const float* Win  = (const float*)d_in[3];
    const float* bias = (const float*)d_in[4];
    const float* tau  = (const float*)d_in[5];
    const float* mw   = (const float*)d_in[6];
    const float* mb   = (const float*)d_in[7];
    float* out = (float*)d_out;

    const int smem_bytes = (1024 * 32 + 1024 * 16 + 16 * 512) * (int)sizeof(float); // 229376
    cudaFuncSetAttribute(liquid_kernel, cudaFuncAttributeMaxDynamicSharedMemorySize,
                         smem_bytes);

    alpha_kernel<<<1, 64>>>(comp, mw, mb, tau);
    zero_hT<<<(2 * NH * NB + 1023) / 1024, 1024>>>();
    dim3 gemm_grid(NH / 128, (NB * NS) / 128);   // (8, 256)
    gemm_u<<<gemm_grid, 256>>>(x, Win, bias);
    liquid_kernel<<<NCTA, 512, smem_bytes>>>(Wrec, out);
}